// round 12
// baseline (speedup 1.0000x reference)
#include <cuda_runtime.h>

#define S_LEN 4096
#define HID 2048
#define NLAYERS 4

// ---------------- scan config (R5/R9/R11 proven geometry) ----------------
#define GBLK 128          // persistent blocks; all co-resident
#define ROWS_PER_BLK 16   // 2048 / 128
#define SCAN_TPB 512
#define KPT 64            // k-elements per thread (reg-resident)

// ---------------- barrier sharding (R11 proven) ----------------
#define NBAR 8
#define BAR_STRIDE 64     // 256 B between counters
#define BLKS_PER_BAR (GBLK / NBAR)

// ---------------- shadow-GEMM tiling ----------------
#define SH_ROWS 32        // timestep rows per phase
#define SH_KCH 64         // k-chunk per step (32 steps/phase -> full 2048)
#define WS_STRIDE 68      // W_s row stride in floats (16B-aligned, 2-way max)

// ---------------- GEMM config ----------------
#define BK 16

// ---------------- scratch (static device globals) ----------
__device__ float g_xw0[S_LEN * HID];    // xw ping
__device__ float g_xw1[S_LEN * HID];    // xw pong
__device__ float g_buf0[S_LEN * HID];   // layer output ping
__device__ float g_buf1[S_LEN * HID];   // layer output pong
__device__ float g_h[2][HID];           // hidden-state ping-pong
__device__ unsigned g_bars[NBAR * BAR_STRIDE];

// ---------------- f32x2 helpers (proven R4/R5) ----------------
__device__ __forceinline__ void fma2(unsigned long long& d, unsigned long long a,
                                     unsigned long long b, unsigned long long c) {
    asm("fma.rn.f32x2 %0, %1, %2, %3;" : "=l"(d) : "l"(a), "l"(b), "l"(c));
}
__device__ __forceinline__ unsigned long long pack2(float lo, float hi) {
    unsigned long long r;
    asm("mov.b64 %0, {%1, %2};" : "=l"(r) : "f"(lo), "f"(hi));
    return r;
}
__device__ __forceinline__ float2 unpack2(unsigned long long v) {
    float2 f;
    asm("mov.b64 {%0, %1}, %2;" : "=f"(f.x), "=f"(f.y) : "l"(v));
    return f;
}

// ---------------------------------------------------------------------------
// reset: zero barrier counters + hidden state (per layer)
// ---------------------------------------------------------------------------
__global__ void reset_kernel() {
    int i = threadIdx.x;
    float* h = &g_h[0][0];
    for (int j = i; j < 2 * HID; j += blockDim.x) h[j] = 0.0f;
    for (int j = i; j < NBAR * BAR_STRIDE; j += blockDim.x) g_bars[j] = 0u;
}

// ---------------------------------------------------------------------------
// GEMM (FROZEN, passing since R4) — now used ONLY for layer 0's xw.
// ---------------------------------------------------------------------------
__global__ void __launch_bounds__(256, 2) gemm_kernel(const float* __restrict__ A,
                                                      const float* __restrict__ B,
                                                      float* __restrict__ C) {
    const int K = HID;
    const int N = HID;
    __shared__ float As[2][BK][128];
    __shared__ float Bs[2][BK][128];

    const int tid  = threadIdx.x;
    const int tx   = tid & 15;
    const int ty   = tid >> 4;
    const int lrow = tid >> 1;
    const int lk   = (tid & 1) * 8;

    const float* Ap = A + (size_t)(blockIdx.y * 128 + lrow) * K + lk;
    const float* Bp = B + (size_t)(blockIdx.x * 128 + lrow) * K + lk;

    unsigned long long acc2[8][4];
    const unsigned long long z2 = pack2(0.0f, 0.0f);
#pragma unroll
    for (int i = 0; i < 8; i++)
#pragma unroll
        for (int j = 0; j < 4; j++) acc2[i][j] = z2;

    {
        float4 a0 = *(const float4*)(Ap);
        float4 a1 = *(const float4*)(Ap + 4);
        float4 b0 = *(const float4*)(Bp);
        float4 b1 = *(const float4*)(Bp + 4);
        As[0][lk + 0][lrow] = a0.x; As[0][lk + 1][lrow] = a0.y;
        As[0][lk + 2][lrow] = a0.z; As[0][lk + 3][lrow] = a0.w;
        As[0][lk + 4][lrow] = a1.x; As[0][lk + 5][lrow] = a1.y;
        As[0][lk + 6][lrow] = a1.z; As[0][lk + 7][lrow] = a1.w;
        Bs[0][lk + 0][lrow] = b0.x; Bs[0][lk + 1][lrow] = b0.y;
        Bs[0][lk + 2][lrow] = b0.z; Bs[0][lk + 3][lrow] = b0.w;
        Bs[0][lk + 4][lrow] = b1.x; Bs[0][lk + 5][lrow] = b1.y;
        Bs[0][lk + 6][lrow] = b1.z; Bs[0][lk + 7][lrow] = b1.w;
    }
    __syncthreads();

    int cur = 0;
    for (int k0 = BK; k0 <= K; k0 += BK) {
        float4 na0, na1, nb0, nb1;
        const bool more = (k0 < K);
        if (more) {
            na0 = *(const float4*)(Ap + k0);
            na1 = *(const float4*)(Ap + k0 + 4);
            nb0 = *(const float4*)(Bp + k0);
            nb1 = *(const float4*)(Bp + k0 + 4);
        }

#pragma unroll
        for (int kk = 0; kk < BK; kk++) {
            float4 a0 = *(const float4*)&As[cur][kk][ty * 8];
            float4 a1 = *(const float4*)&As[cur][kk][ty * 8 + 4];
            ulonglong2 bp0 = *(const ulonglong2*)&Bs[cur][kk][tx * 8];
            ulonglong2 bp1 = *(const ulonglong2*)&Bs[cur][kk][tx * 8 + 4];
            float a[8] = {a0.x, a0.y, a0.z, a0.w, a1.x, a1.y, a1.z, a1.w};
#pragma unroll
            for (int i = 0; i < 8; i++) {
                unsigned long long aa = pack2(a[i], a[i]);
                fma2(acc2[i][0], aa, bp0.x, acc2[i][0]);
                fma2(acc2[i][1], aa, bp0.y, acc2[i][1]);
                fma2(acc2[i][2], aa, bp1.x, acc2[i][2]);
                fma2(acc2[i][3], aa, bp1.y, acc2[i][3]);
            }
        }

        if (more) {
            int nxt = cur ^ 1;
            As[nxt][lk + 0][lrow] = na0.x; As[nxt][lk + 1][lrow] = na0.y;
            As[nxt][lk + 2][lrow] = na0.z; As[nxt][lk + 3][lrow] = na0.w;
            As[nxt][lk + 4][lrow] = na1.x; As[nxt][lk + 5][lrow] = na1.y;
            As[nxt][lk + 6][lrow] = na1.z; As[nxt][lk + 7][lrow] = na1.w;
            Bs[nxt][lk + 0][lrow] = nb0.x; Bs[nxt][lk + 1][lrow] = nb0.y;
            Bs[nxt][lk + 2][lrow] = nb0.z; Bs[nxt][lk + 3][lrow] = nb0.w;
            Bs[nxt][lk + 4][lrow] = nb1.x; Bs[nxt][lk + 5][lrow] = nb1.y;
            Bs[nxt][lk + 6][lrow] = nb1.z; Bs[nxt][lk + 7][lrow] = nb1.w;
            __syncthreads();
            cur = nxt;
        }
    }

#pragma unroll
    for (int i = 0; i < 8; i++) {
        float* Cp = C + (size_t)(blockIdx.y * 128 + ty * 8 + i) * N +
                    blockIdx.x * 128 + tx * 8;
        float2 c0 = unpack2(acc2[i][0]);
        float2 c1 = unpack2(acc2[i][1]);
        float2 c2 = unpack2(acc2[i][2]);
        float2 c3 = unpack2(acc2[i][3]);
        *(float4*)(Cp + 0) = make_float4(c0.x, c0.y, c1.x, c1.y);
        *(float4*)(Cp + 4) = make_float4(c2.x, c2.y, c3.x, c3.y);
    }
}

// ---------------------------------------------------------------------------
// Persistent recurrence + SHADOW GEMM.
// Sync protocol byte-identical to R11 (sharded counters, red.release arrival,
// ld.acquire poll x8, bar relay). New: between release and poll, each block
// accumulates xw_next[r, 16b..16b+16) = y[r,:] @ W_ih_next for rows r<=t-33
// (finalized, visibility guaranteed by the per-step acquire chain). 32-row
// phase over 32 steps, k-chunk 64/step = 64 MAC/thread/step. Rows 4032..4095
// finished in a one-time tail after the loop.
// ---------------------------------------------------------------------------
__global__ void __launch_bounds__(SCAN_TPB, 1) scan_kernel(
    const float* __restrict__ xw, const float* __restrict__ whh,
    float* __restrict__ y, float* __restrict__ hlast,
    const float* __restrict__ wn,   // W_ih of next layer (nullptr: no shadow)
    float* __restrict__ xwn) {      // xw output for next layer
    __shared__ float hbuf[HID];
    __shared__ float part[16][ROWS_PER_BLK];
    __shared__ float ysh[SH_ROWS][SH_KCH];        // 8 KB y tile
    __shared__ float wsh[16 * WS_STRIDE];         // 4.25 KB W tile

    const int tid  = threadIdx.x;
    const int row  = tid & 15;
    const int kg   = tid >> 4;
    const int k0   = kg * KPT;
    const int rowG = blockIdx.x * ROWS_PER_BLK + row;
    const int warp = tid >> 5;
    const int lane = tid & 31;
    const int col  = blockIdx.x * ROWS_PER_BLK + tid;  // used when tid<16
    const int cbase = blockIdx.x * ROWS_PER_BLK;       // shadow output cols
    unsigned* ourbar = &g_bars[(blockIdx.x & (NBAR - 1)) * BAR_STRIDE];

    // W_hh slice -> registers as f32x2 pairs
    unsigned long long wp[KPT / 2];
    {
        const float* wr = whh + (size_t)rowG * HID + k0;
#pragma unroll
        for (int i = 0; i < KPT / 4; i++) {
            ulonglong2 v = *(const ulonglong2*)(wr + i * 4);
            wp[2 * i]     = v.x;
            wp[2 * i + 1] = v.y;
        }
    }

    const bool shadow = (wn != nullptr);
    float xacc = 0.0f;                 // shadow accumulator (phase-carried)
    const int stl = tid >> 4;          // shadow row-in-tile (0..31)
    const int sc  = tid & 15;          // shadow col-in-block (0..15)

    int p = 0;
    for (int t = 0; t < S_LEN; ++t) {
        // prefetch xw early (immutable within the layer)
        float xwv = 0.0f;
        if (tid < ROWS_PER_BLK) xwv = __ldg(&xw[(size_t)t * HID + col]);

        // broadcast h_{t-1}
        float4 hv4 = __ldcg((const float4*)&g_h[p][tid * 4]);
        *(float4*)&hbuf[tid * 4] = hv4;
        __syncthreads();

        // dot product: 32 packed FFMA2 from register-resident W
        unsigned long long a0, a1, a2, a3;
        a0 = a1 = a2 = a3 = pack2(0.0f, 0.0f);
#pragma unroll
        for (int i = 0; i < KPT / 8; i++) {
            ulonglong2 h0 = *(const ulonglong2*)&hbuf[k0 + i * 8];
            ulonglong2 h1 = *(const ulonglong2*)&hbuf[k0 + i * 8 + 4];
            fma2(a0, wp[4 * i + 0], h0.x, a0);
            fma2(a1, wp[4 * i + 1], h0.y, a1);
            fma2(a2, wp[4 * i + 2], h1.x, a2);
            fma2(a3, wp[4 * i + 3], h1.y, a3);
        }
        float2 f0 = unpack2(a0), f1 = unpack2(a1);
        float2 f2 = unpack2(a2), f3 = unpack2(a3);
        float acc = ((f0.x + f0.y) + (f1.x + f1.y)) +
                    ((f2.x + f2.y) + (f3.x + f3.y));

        acc += __shfl_down_sync(0xffffffffu, acc, 16);
        if (lane < 16) part[warp][lane] = acc;
        __syncthreads();

        // final reduce + relu + publish h + sharded release
        if (tid < ROWS_PER_BLK) {
            float s01 = part[0][tid]  + part[1][tid];
            float s23 = part[2][tid]  + part[3][tid];
            float s45 = part[4][tid]  + part[5][tid];
            float s67 = part[6][tid]  + part[7][tid];
            float s89 = part[8][tid]  + part[9][tid];
            float sab = part[10][tid] + part[11][tid];
            float scd = part[12][tid] + part[13][tid];
            float sef = part[14][tid] + part[15][tid];
            float s = ((s01 + s23) + (s45 + s67)) + ((s89 + sab) + (scd + sef));
            float hv = fmaxf(s + xwv, 0.0f);
            g_h[p ^ 1][col] = hv;
            __syncwarp(0x0000ffffu);
            if (tid == 0) {
                asm volatile("red.release.gpu.global.add.u32 [%0], %1;"
                             :: "l"(ourbar), "r"(1u) : "memory");
            }
            y[(size_t)t * HID + col] = hv;
            if (hlast != nullptr && t == S_LEN - 1) hlast[col] = hv;
        }

        // ---- SHADOW GEMM slice (hidden under the barrier wait) ----
        if (shadow && t >= 2 * SH_ROWS) {
            const int ph = t >> 5;          // phase index
            const int sl = t & 31;          // slice within phase
            const int r0 = (ph - 2) * SH_ROWS;
            const int kk0 = sl * SH_KCH;
            // stage y[r0+stl, kk0..+64) (all threads) and W rows (tid<256)
            float4 yv = __ldcg((const float4*)&y[(size_t)(r0 + stl) * HID +
                                                 kk0 + sc * 4]);
            *(float4*)&ysh[stl][sc * 4] = yv;
            if (tid < 256) {
                int wr = tid >> 4, wk = (tid & 15) * 4;
                float4 wv = *(const float4*)&wn[(size_t)(cbase + wr) * HID +
                                                kk0 + wk];
                *(float4*)&wsh[wr * WS_STRIDE + wk] = wv;
            }
            __syncthreads();
            float sa = (sl == 0) ? 0.0f : xacc;
#pragma unroll
            for (int j = 0; j < SH_KCH / 4; j++) {
                float4 ya = *(const float4*)&ysh[stl][j * 4];
                float4 wa = *(const float4*)&wsh[sc * WS_STRIDE + j * 4];
                sa = fmaf(ya.x, wa.x, sa);
                sa = fmaf(ya.y, wa.y, sa);
                sa = fmaf(ya.z, wa.z, sa);
                sa = fmaf(ya.w, wa.w, sa);
            }
            xacc = sa;
            if (sl == 31)
                xwn[(size_t)(r0 + stl) * HID + cbase + sc] = xacc;
        }

        // sharded barrier wait (threads 0..7), bar relays to block
        if (tid < NBAR) {
            const unsigned target = (unsigned)(t + 1) * (unsigned)BLKS_PER_BAR;
            const unsigned* bp = &g_bars[tid * BAR_STRIDE];
            unsigned v;
            do {
                asm volatile("ld.acquire.gpu.global.u32 %0, [%1];"
                             : "=r"(v) : "l"(bp) : "memory");
            } while (v < target);
        }
        __syncthreads();
        p ^= 1;
    }

    // ---- shadow tail: rows [4096-2*SH_ROWS, 4096) (all y final now) ----
    if (shadow) {
        for (int r = S_LEN - 2 * SH_ROWS + stl; r < S_LEN; r += SH_ROWS) {
            float sa = 0.0f;
            const float* yr_ = &y[(size_t)r * HID];
            const float* wr_ = &wn[(size_t)(cbase + sc) * HID];
            for (int k = 0; k < HID; k += 4) {
                float4 yv = __ldcg((const float4*)(yr_ + k));
                float4 wv = *(const float4*)(wr_ + k);
                sa = fmaf(yv.x, wv.x, sa);
                sa = fmaf(yv.y, wv.y, sa);
                sa = fmaf(yv.z, wv.z, sa);
                sa = fmaf(yv.w, wv.w, sa);
            }
            xwn[(size_t)r * HID + cbase + sc] = sa;
        }
    }
}

// ---------------------------------------------------------------------------
// host launcher: gemm only for layer 0; layers 1-3 xw come from shadow GEMM.
// ---------------------------------------------------------------------------
extern "C" void kernel_launch(void* const* d_in, const int* in_sizes, int n_in,
                              void* d_out, int out_size) {
    const float* x0  = (const float*)d_in[0];
    const float* wih = (const float*)d_in[1];
    const float* whh = (const float*)d_in[2];
    float* out = (float*)d_out;

    void *p_xw0, *p_xw1, *p_b0, *p_b1;
    cudaGetSymbolAddress(&p_xw0, g_xw0);
    cudaGetSymbolAddress(&p_xw1, g_xw1);
    cudaGetSymbolAddress(&p_b0, g_buf0);
    cudaGetSymbolAddress(&p_b1, g_buf1);
    float* xwp[2]  = {(float*)p_xw0, (float*)p_xw1};
    float* bufs[2] = {(float*)p_b0, (float*)p_b1};

    float* hlast = (out_size >= S_LEN * HID + HID) ? out + (size_t)S_LEN * HID
                                                   : nullptr;

    dim3 ggrid(HID / 128, S_LEN / 128);
    reset_kernel<<<1, 512>>>();
    gemm_kernel<<<ggrid, 256>>>(x0, wih, xwp[0]);   // layer 0 xw only

    for (int L = 0; L < NLAYERS; ++L) {
        if (L > 0) reset_kernel<<<1, 512>>>();
        float* yout = (L == NLAYERS - 1) ? out : bufs[L & 1];
        const float* wn = (L < NLAYERS - 1)
                              ? wih + (size_t)(L + 1) * HID * HID
                              : nullptr;
        float* xwn = (L < NLAYERS - 1) ? xwp[(L + 1) & 1] : nullptr;
        scan_kernel<<<GBLK, SCAN_TPB>>>(xwp[L & 1],
                                        whh + (size_t)L * HID * HID, yout,
                                        (L == NLAYERS - 1) ? hlast : nullptr,
                                        wn, xwn);
    }
}

// round 13
// speedup vs baseline: 1.2545x; 1.2545x over previous
#include <cuda_runtime.h>

#define S_LEN 4096
#define HID 2048
#define NLAYERS 4

// ---------------- scan config (R5/R9/R11 proven geometry) ----------------
#define GBLK 128          // persistent blocks; all co-resident
#define ROWS_PER_BLK 16   // 2048 / 128
#define SCAN_TPB 512
#define KPT 64            // k-elements per thread (reg-resident)

// ---------------- barrier sharding (R11 proven) ----------------
#define NBAR 8
#define BAR_STRIDE 64     // 256 B between counters
#define BLKS_PER_BAR (GBLK / NBAR)

// ---------------- GEMM config ----------------
#define BK 16

// ---------------- scratch (static device globals) ----------
__device__ float g_xw[S_LEN * HID];           // input projection (per layer)
__device__ float g_buf0[S_LEN * HID];         // layer output ping
__device__ float g_buf1[S_LEN * HID];         // layer output pong
__device__ float g_hh[NLAYERS][2][HID];       // per-layer hidden ping-pong
__device__ unsigned g_bars[NBAR * BAR_STRIDE];// sharded counters (monotonic
                                              // across ALL layers; no re-zero)

// ---------------- f32x2 helpers (proven R4/R5) ----------------
__device__ __forceinline__ void fma2(unsigned long long& d, unsigned long long a,
                                     unsigned long long b, unsigned long long c) {
    asm("fma.rn.f32x2 %0, %1, %2, %3;" : "=l"(d) : "l"(a), "l"(b), "l"(c));
}
__device__ __forceinline__ unsigned long long pack2(float lo, float hi) {
    unsigned long long r;
    asm("mov.b64 %0, {%1, %2};" : "=l"(r) : "f"(lo), "f"(hi));
    return r;
}
__device__ __forceinline__ float2 unpack2(unsigned long long v) {
    float2 f;
    asm("mov.b64 {%0, %1}, %2;" : "=f"(f.x), "=f"(f.y) : "l"(v));
    return f;
}

// ---------------------------------------------------------------------------
// reset: ONE launch zeroes all layers' h buffers + all barrier counters.
// Counters are monotonic across layers, so no per-layer re-zero is needed.
// ---------------------------------------------------------------------------
__global__ void reset_kernel() {
    int i = threadIdx.x;
    float* h = &g_hh[0][0][0];
    for (int j = i; j < NLAYERS * 2 * HID; j += blockDim.x) h[j] = 0.0f;
    for (int j = i; j < NBAR * BAR_STRIDE; j += blockDim.x) g_bars[j] = 0u;
}

// ---------------------------------------------------------------------------
// GEMM (FROZEN, passing since R4): C[i,j] = sum_k A[i,k]*B[j,k]
// ---------------------------------------------------------------------------
__global__ void __launch_bounds__(256, 2) gemm_kernel(const float* __restrict__ A,
                                                      const float* __restrict__ B,
                                                      float* __restrict__ C) {
    const int K = HID;
    const int N = HID;
    __shared__ float As[2][BK][128];
    __shared__ float Bs[2][BK][128];

    const int tid  = threadIdx.x;
    const int tx   = tid & 15;
    const int ty   = tid >> 4;
    const int lrow = tid >> 1;
    const int lk   = (tid & 1) * 8;

    const float* Ap = A + (size_t)(blockIdx.y * 128 + lrow) * K + lk;
    const float* Bp = B + (size_t)(blockIdx.x * 128 + lrow) * K + lk;

    unsigned long long acc2[8][4];
    const unsigned long long z2 = pack2(0.0f, 0.0f);
#pragma unroll
    for (int i = 0; i < 8; i++)
#pragma unroll
        for (int j = 0; j < 4; j++) acc2[i][j] = z2;

    {
        float4 a0 = *(const float4*)(Ap);
        float4 a1 = *(const float4*)(Ap + 4);
        float4 b0 = *(const float4*)(Bp);
        float4 b1 = *(const float4*)(Bp + 4);
        As[0][lk + 0][lrow] = a0.x; As[0][lk + 1][lrow] = a0.y;
        As[0][lk + 2][lrow] = a0.z; As[0][lk + 3][lrow] = a0.w;
        As[0][lk + 4][lrow] = a1.x; As[0][lk + 5][lrow] = a1.y;
        As[0][lk + 6][lrow] = a1.z; As[0][lk + 7][lrow] = a1.w;
        Bs[0][lk + 0][lrow] = b0.x; Bs[0][lk + 1][lrow] = b0.y;
        Bs[0][lk + 2][lrow] = b0.z; Bs[0][lk + 3][lrow] = b0.w;
        Bs[0][lk + 4][lrow] = b1.x; Bs[0][lk + 5][lrow] = b1.y;
        Bs[0][lk + 6][lrow] = b1.z; Bs[0][lk + 7][lrow] = b1.w;
    }
    __syncthreads();

    int cur = 0;
    for (int k0 = BK; k0 <= K; k0 += BK) {
        float4 na0, na1, nb0, nb1;
        const bool more = (k0 < K);
        if (more) {
            na0 = *(const float4*)(Ap + k0);
            na1 = *(const float4*)(Ap + k0 + 4);
            nb0 = *(const float4*)(Bp + k0);
            nb1 = *(const float4*)(Bp + k0 + 4);
        }

#pragma unroll
        for (int kk = 0; kk < BK; kk++) {
            float4 a0 = *(const float4*)&As[cur][kk][ty * 8];
            float4 a1 = *(const float4*)&As[cur][kk][ty * 8 + 4];
            ulonglong2 bp0 = *(const ulonglong2*)&Bs[cur][kk][tx * 8];
            ulonglong2 bp1 = *(const ulonglong2*)&Bs[cur][kk][tx * 8 + 4];
            float a[8] = {a0.x, a0.y, a0.z, a0.w, a1.x, a1.y, a1.z, a1.w};
#pragma unroll
            for (int i = 0; i < 8; i++) {
                unsigned long long aa = pack2(a[i], a[i]);
                fma2(acc2[i][0], aa, bp0.x, acc2[i][0]);
                fma2(acc2[i][1], aa, bp0.y, acc2[i][1]);
                fma2(acc2[i][2], aa, bp1.x, acc2[i][2]);
                fma2(acc2[i][3], aa, bp1.y, acc2[i][3]);
            }
        }

        if (more) {
            int nxt = cur ^ 1;
            As[nxt][lk + 0][lrow] = na0.x; As[nxt][lk + 1][lrow] = na0.y;
            As[nxt][lk + 2][lrow] = na0.z; As[nxt][lk + 3][lrow] = na0.w;
            As[nxt][lk + 4][lrow] = na1.x; As[nxt][lk + 5][lrow] = na1.y;
            As[nxt][lk + 6][lrow] = na1.z; As[nxt][lk + 7][lrow] = na1.w;
            Bs[nxt][lk + 0][lrow] = nb0.x; Bs[nxt][lk + 1][lrow] = nb0.y;
            Bs[nxt][lk + 2][lrow] = nb0.z; Bs[nxt][lk + 3][lrow] = nb0.w;
            Bs[nxt][lk + 4][lrow] = nb1.x; Bs[nxt][lk + 5][lrow] = nb1.y;
            Bs[nxt][lk + 6][lrow] = nb1.z; Bs[nxt][lk + 7][lrow] = nb1.w;
            __syncthreads();
            cur = nxt;
        }
    }

#pragma unroll
    for (int i = 0; i < 8; i++) {
        float* Cp = C + (size_t)(blockIdx.y * 128 + ty * 8 + i) * N +
                    blockIdx.x * 128 + tx * 8;
        float2 c0 = unpack2(acc2[i][0]);
        float2 c1 = unpack2(acc2[i][1]);
        float2 c2 = unpack2(acc2[i][2]);
        float2 c3 = unpack2(acc2[i][3]);
        *(float4*)(Cp + 0) = make_float4(c0.x, c0.y, c1.x, c1.y);
        *(float4*)(Cp + 4) = make_float4(c2.x, c2.y, c3.x, c3.y);
    }
}

// ---------------------------------------------------------------------------
// Persistent recurrence: h_t = relu(xw_t + W_hh @ h_{t-1})
// Byte-identical protocol to PASSING R11 (sharded counters, red.release
// arrival, ld.acquire poll x8, bar relay). Only change: counters are
// monotonic across layers; wait target = (tbase + t + 1)*BLKS_PER_BAR with
// tbase = layer*S_LEN, and each layer uses its own h ping-pong (hg).
// ---------------------------------------------------------------------------
__global__ void __launch_bounds__(SCAN_TPB, 1) scan_kernel(
    const float* __restrict__ xw, const float* __restrict__ whh,
    float* __restrict__ y, float* __restrict__ hlast,
    float* __restrict__ hg, unsigned tbase) {
    __shared__ float hbuf[HID];
    __shared__ float part[16][ROWS_PER_BLK];

    const int tid  = threadIdx.x;
    const int row  = tid & 15;
    const int kg   = tid >> 4;
    const int k0   = kg * KPT;
    const int rowG = blockIdx.x * ROWS_PER_BLK + row;
    const int warp = tid >> 5;
    const int lane = tid & 31;
    const int col  = blockIdx.x * ROWS_PER_BLK + tid;  // used when tid<16
    unsigned* ourbar = &g_bars[(blockIdx.x & (NBAR - 1)) * BAR_STRIDE];

    // W_hh slice -> registers as f32x2 pairs
    unsigned long long wp[KPT / 2];
    {
        const float* wr = whh + (size_t)rowG * HID + k0;
#pragma unroll
        for (int i = 0; i < KPT / 4; i++) {
            ulonglong2 v = *(const ulonglong2*)(wr + i * 4);
            wp[2 * i]     = v.x;
            wp[2 * i + 1] = v.y;
        }
    }

    int p = 0;
    for (int t = 0; t < S_LEN; ++t) {
        // prefetch xw early (immutable within the layer)
        float xwv = 0.0f;
        if (tid < ROWS_PER_BLK) xwv = __ldg(&xw[(size_t)t * HID + col]);

        // broadcast h_{t-1}: one float4 per thread, L2 load
        float4 hv4 = __ldcg((const float4*)&hg[p * HID + tid * 4]);
        *(float4*)&hbuf[tid * 4] = hv4;
        __syncthreads();

        // dot product: 32 packed FFMA2 from register-resident W
        unsigned long long a0, a1, a2, a3;
        a0 = a1 = a2 = a3 = pack2(0.0f, 0.0f);
#pragma unroll
        for (int i = 0; i < KPT / 8; i++) {
            ulonglong2 h0 = *(const ulonglong2*)&hbuf[k0 + i * 8];
            ulonglong2 h1 = *(const ulonglong2*)&hbuf[k0 + i * 8 + 4];
            fma2(a0, wp[4 * i + 0], h0.x, a0);
            fma2(a1, wp[4 * i + 1], h0.y, a1);
            fma2(a2, wp[4 * i + 2], h1.x, a2);
            fma2(a3, wp[4 * i + 3], h1.y, a3);
        }
        float2 f0 = unpack2(a0), f1 = unpack2(a1);
        float2 f2 = unpack2(a2), f3 = unpack2(a3);
        float acc = ((f0.x + f0.y) + (f1.x + f1.y)) +
                    ((f2.x + f2.y) + (f3.x + f3.y));

        // combine the two k-groups living in one warp
        acc += __shfl_down_sync(0xffffffffu, acc, 16);
        if (lane < 16) part[warp][lane] = acc;
        __syncthreads();

        // final reduce (tree) + relu + publish h + sharded release
        if (tid < ROWS_PER_BLK) {
            float s01 = part[0][tid]  + part[1][tid];
            float s23 = part[2][tid]  + part[3][tid];
            float s45 = part[4][tid]  + part[5][tid];
            float s67 = part[6][tid]  + part[7][tid];
            float s89 = part[8][tid]  + part[9][tid];
            float sab = part[10][tid] + part[11][tid];
            float scd = part[12][tid] + part[13][tid];
            float sef = part[14][tid] + part[15][tid];
            float s = ((s01 + s23) + (s45 + s67)) + ((s89 + sab) + (scd + sef));
            float hv = fmaxf(s + xwv, 0.0f);
            hg[(p ^ 1) * HID + col] = hv;      // protocol state: before release
            __syncwarp(0x0000ffffu);           // order 16 h-stores in warp 0
            if (tid == 0) {
                asm volatile("red.release.gpu.global.add.u32 [%0], %1;"
                             :: "l"(ourbar), "r"(1u) : "memory");
            }
            // outputs (read only across kernel boundary): off critical path
            y[(size_t)t * HID + col] = hv;
            if (hlast != nullptr && t == S_LEN - 1) hlast[col] = hv;
        }

        // threads 0..7 each poll their own counter; bar relays to block
        if (tid < NBAR) {
            const unsigned target =
                (tbase + (unsigned)(t + 1)) * (unsigned)BLKS_PER_BAR;
            const unsigned* bp = &g_bars[tid * BAR_STRIDE];
            unsigned v;
            do {
                asm volatile("ld.acquire.gpu.global.u32 %0, [%1];"
                             : "=r"(v) : "l"(bp) : "memory");
            } while (v < target);
        }
        __syncthreads();
        p ^= 1;
    }
}

// ---------------------------------------------------------------------------
// host launcher: reset, gemm, scan x4  (launch #5 = scan of layer 3 -> ncu
// -s 5 -c 1 finally profiles the scan kernel instead of reset).
// ---------------------------------------------------------------------------
extern "C" void kernel_launch(void* const* d_in, const int* in_sizes, int n_in,
                              void* d_out, int out_size) {
    const float* x0  = (const float*)d_in[0];
    const float* wih = (const float*)d_in[1];
    const float* whh = (const float*)d_in[2];
    float* out = (float*)d_out;

    void *p_xw, *p_b0, *p_b1, *p_hh;
    cudaGetSymbolAddress(&p_xw, g_xw);
    cudaGetSymbolAddress(&p_b0, g_buf0);
    cudaGetSymbolAddress(&p_b1, g_buf1);
    cudaGetSymbolAddress(&p_hh, g_hh);
    float* bufs[2] = {(float*)p_b0, (float*)p_b1};

    float* hlast = (out_size >= S_LEN * HID + HID) ? out + (size_t)S_LEN * HID
                                                   : nullptr;

    reset_kernel<<<1, 512>>>();                       // launch 0

    const float* x = x0;
    dim3 ggrid(HID / 128, S_LEN / 128);
    for (int L = 0; L < NLAYERS; ++L) {
        gemm_kernel<<<ggrid, 256>>>(x, wih + (size_t)L * HID * HID,
                                    (float*)p_xw);    // launches 1,?  (L=0: #1)
        float* yout = (L == NLAYERS - 1) ? out : bufs[L & 1];
        scan_kernel<<<GBLK, SCAN_TPB>>>((const float*)p_xw,
                                        whh + (size_t)L * HID * HID, yout,
                                        (L == NLAYERS - 1) ? hlast : nullptr,
                                        (float*)p_hh + (size_t)L * 2 * HID,
                                        (unsigned)(L * S_LEN));
        x = yout;
    }
    // NOTE: gemm must run before each layer's scan, so the true order is
    // reset, gemm0, scan0, gemm1, scan1, gemm2, scan2, gemm3, scan3
    // -> launch #5 = gemm2?  No: indices 0..8 give #5 = gemm2... but gemm
    // depends on scan(L-1) output; we cannot hoist.  #5=gemm2, #6=scan2.
}